// round 4
// baseline (speedup 1.0000x reference)
#include <cuda_runtime.h>
#include <math.h>

// Problem constants
#define NT   1024          // tokens
#define ND   2048          // hidden dim
#define NE   32            // experts
#define NI   1408          // routed intermediate
#define NSI  2816          // shared intermediate
#define NG   8             // groups
#define EPG  4             // experts per group
#define NA   (NT * 4)      // total assignments (top_k = 4, exact)

typedef unsigned long long u64;

// packed f32x2 FMA: d = a*b + d (lane-wise fp32, round-to-nearest) — sm_100a+
__device__ __forceinline__ void fma2(u64& d, u64 a, u64 b) {
    asm("fma.rn.f32x2 %0, %1, %2, %0;" : "+l"(d) : "l"(a), "l"(b));
}
__device__ __forceinline__ float2 unpack2(u64 v) {
    float2 r; asm("mov.b64 {%0, %1}, %2;" : "=f"(r.x), "=f"(r.y) : "l"(v)); return r;
}

// ---------------- device scratch (no allocation allowed) ----------------
__device__ float g_h [NA * NI];    // routed  silu(x@Wg)*(x@Wu)
__device__ float g_hs[NT * NSI];   // shared  silu(x@Sg)*(x@Su)
__device__ int   g_rowlist[NA];    // assignment row -> token id (grouped by expert)
__device__ float g_roww  [NA];     // assignment row -> combine weight
__device__ int   g_counts [NE];
__device__ int   g_offsets[NE];
__device__ int   g_cursor [NE];
__device__ int   g_tid4[NA];       // per-token top-4 expert ids
__device__ float g_tw4 [NA];       // per-token top-4 weights (normalized)

// ---------------- tiny kernels ----------------
__global__ void zero_kernel() {
    int i = threadIdx.x;
    if (i < NE) { g_counts[i] = 0; g_cursor[i] = 0; }
}

// One block per token: logits = x@gate_w^T + gate_b ; sigmoid ; biased grouped top-k.
__global__ void gate_kernel(const float* __restrict__ x,
                            const float* __restrict__ gw,
                            const float* __restrict__ gb) {
    __shared__ float xs[ND];
    __shared__ float logit[NE];
    int t = blockIdx.x;
    for (int k = threadIdx.x; k < ND; k += 256) xs[k] = x[(size_t)t * ND + k];
    __syncthreads();

    int e = threadIdx.x >> 3;         // 32 experts x 8 threads
    int j = threadIdx.x & 7;
    const float* w = gw + (size_t)e * ND;
    float s = 0.f;
    for (int k = j; k < ND; k += 8) s += xs[k] * w[k];
    s += __shfl_xor_sync(0xffffffffu, s, 1);
    s += __shfl_xor_sync(0xffffffffu, s, 2);
    s += __shfl_xor_sync(0xffffffffu, s, 4);
    if (j == 0) logit[e] = s + gb[e];
    __syncthreads();

    if (threadIdx.x == 0) {
        float sc[NE], scb[NE];
        #pragma unroll
        for (int i = 0; i < NE; i++) {
            float v = 1.f / (1.f + expf(-logit[i]));
            sc[i]  = v;             // unbiased sigmoid (used for weights)
            scb[i] = v + gb[i];     // biased score (used for choice)
        }
        // group score = sum of top-2 biased scores in each group of 4
        float gs[NG];
        #pragma unroll
        for (int g = 0; g < NG; g++) {
            float m1 = -1e30f, m2 = -1e30f;
            #pragma unroll
            for (int q = 0; q < EPG; q++) {
                float v = scb[g * EPG + q];
                if (v > m1) { m2 = m1; m1 = v; } else if (v > m2) { m2 = v; }
            }
            gs[g] = m1 + m2;
        }
        // top-4 groups (strict '>' scan in ascending index order == lax.top_k tie rule)
        bool gsel[NG];
        #pragma unroll
        for (int g = 0; g < NG; g++) gsel[g] = false;
        for (int r = 0; r < 4; r++) {
            float best = -1e30f; int bi = 0;
            for (int g = 0; g < NG; g++)
                if (!gsel[g] && gs[g] > best) { best = gs[g]; bi = g; }
            gsel[bi] = true;
        }
        // masked scores: exactly jnp.where(mask, scb, 0.0)
        float tmp[NE];
        #pragma unroll
        for (int i = 0; i < NE; i++) tmp[i] = gsel[i / EPG] ? scb[i] : 0.0f;
        // top-4 experts of tmp
        int ids[4]; float tw[4]; float wsum = 0.f;
        for (int r = 0; r < 4; r++) {
            float best = -1e30f; int bi = 0;
            for (int i = 0; i < NE; i++)
                if (tmp[i] > best) { best = tmp[i]; bi = i; }
            tmp[bi] = -1e30f;
            ids[r] = bi;
            tw[r] = sc[bi];           // weights from UNbiased sigmoid scores
            wsum += tw[r];
        }
        float inv = 1.f / wsum;
        for (int r = 0; r < 4; r++) {
            g_tid4[t * 4 + r] = ids[r];
            g_tw4 [t * 4 + r] = tw[r] * inv;
            atomicAdd(&g_counts[ids[r]], 1);
        }
    }
}

__global__ void scan_kernel() {   // 32 threads: exclusive scan of counts
    int tid = threadIdx.x;
    int c = g_counts[tid];
    int v = c;
    #pragma unroll
    for (int o = 1; o < 32; o <<= 1) {
        int u = __shfl_up_sync(0xffffffffu, v, o);
        if (tid >= o) v += u;
    }
    g_offsets[tid] = v - c;
}

__global__ void scatter_kernel() {
    int i = blockIdx.x * blockDim.x + threadIdx.x;
    if (i >= NA) return;
    int t = i >> 2;
    int e = g_tid4[i];
    int pos = atomicAdd(&g_cursor[e], 1);
    int row = g_offsets[e] + pos;
    g_rowlist[row] = t;
    g_roww[row]   = g_tw4[i];
}

// ---------------- GEMM 1: H = silu(A@Wg) * (A@Wu) ----------------
// BM=128, BN=64, BK=16, 256 threads, 8x4 per-thread tile per matrix.
// Inner loop uses packed fma.rn.f32x2; A tile stored duplicated {v,v} in SMEM
// so the broadcast operand is pre-packed (no per-iteration mov.b64).
template<int IDIM, bool GATHER>
__global__ void __launch_bounds__(256, 2)
gemm_gated(const float* __restrict__ x,
           const float* __restrict__ Wg,
           const float* __restrict__ Wu) {
    int e   = GATHER ? blockIdx.z : 0;
    int cnt = GATHER ? g_counts[e]  : NT;
    int off = GATHER ? g_offsets[e] : 0;
    int m0  = blockIdx.x * 128;
    if (m0 >= cnt) return;
    int n0  = blockIdx.y * 64;
    const float* wg = Wg + (size_t)e * ND * IDIM;
    const float* wu = Wu + (size_t)e * ND * IDIM;
    float* H = GATHER ? g_h : g_hs;

    __shared__ float2 As2[16][132];   // duplicated-pair A tile, padded
    __shared__ float  Bg[16][68];
    __shared__ float  Bu[16][68];

    int tid = threadIdx.x;
    int tx = tid & 15, ty = tid >> 4;

    // A-tile loader mapping: two float4 per thread
    const float* aptr[2];
    int mA[2], kA[2];
    #pragma unroll
    for (int l = 0; l < 2; l++) {
        int idx = tid + l * 256;
        mA[l] = idx >> 2; kA[l] = (idx & 3) << 2;
        int m = m0 + mA[l];
        int tok;
        if (GATHER) tok = (m < cnt) ? g_rowlist[off + m] : 0;
        else        tok = (m < cnt) ? m : 0;
        aptr[l] = x + (size_t)tok * ND + kA[l];
    }
    // B-tile loader: one float4 per thread per matrix
    int kB = tid >> 4, nB = (tid & 15) << 2;
    const float* bgp = wg + (size_t)kB * IDIM + n0 + nB;
    const float* bup = wu + (size_t)kB * IDIM + n0 + nB;

    u64 accg[8][2], accu[8][2];
    #pragma unroll
    for (int r = 0; r < 8; r++)
        #pragma unroll
        for (int c = 0; c < 2; c++) { accg[r][c] = 0ull; accu[r][c] = 0ull; }

    float4 ra0 = *(const float4*)(aptr[0]);
    float4 ra1 = *(const float4*)(aptr[1]);
    float4 rbg = *(const float4*)(bgp);
    float4 rbu = *(const float4*)(bup);

    for (int kt = 0; kt < ND; kt += 16) {
        As2[kA[0]+0][mA[0]] = make_float2(ra0.x, ra0.x);
        As2[kA[0]+1][mA[0]] = make_float2(ra0.y, ra0.y);
        As2[kA[0]+2][mA[0]] = make_float2(ra0.z, ra0.z);
        As2[kA[0]+3][mA[0]] = make_float2(ra0.w, ra0.w);
        As2[kA[1]+0][mA[1]] = make_float2(ra1.x, ra1.x);
        As2[kA[1]+1][mA[1]] = make_float2(ra1.y, ra1.y);
        As2[kA[1]+2][mA[1]] = make_float2(ra1.z, ra1.z);
        As2[kA[1]+3][mA[1]] = make_float2(ra1.w, ra1.w);
        *(float4*)&Bg[kB][nB] = rbg;
        *(float4*)&Bu[kB][nB] = rbu;
        __syncthreads();
        if (kt + 16 < ND) {
            ra0 = *(const float4*)(aptr[0] + kt + 16);
            ra1 = *(const float4*)(aptr[1] + kt + 16);
            rbg = *(const float4*)(bgp + (size_t)(kt + 16) * IDIM);
            rbu = *(const float4*)(bup + (size_t)(kt + 16) * IDIM);
        }
        #pragma unroll
        for (int kk = 0; kk < 16; kk++) {
            u64 ad[8];
            const ulonglong2* ap = reinterpret_cast<const ulonglong2*>(&As2[kk][ty * 8]);
            ulonglong2 p0 = ap[0], p1 = ap[1], p2 = ap[2], p3 = ap[3];
            ad[0] = p0.x; ad[1] = p0.y; ad[2] = p1.x; ad[3] = p1.y;
            ad[4] = p2.x; ad[5] = p2.y; ad[6] = p3.x; ad[7] = p3.y;
            ulonglong2 bg2 = *reinterpret_cast<const ulonglong2*>(&Bg[kk][tx * 4]);
            ulonglong2 bu2 = *reinterpret_cast<const ulonglong2*>(&Bu[kk][tx * 4]);
            #pragma unroll
            for (int r = 0; r < 8; r++) {
                fma2(accg[r][0], ad[r], bg2.x);
                fma2(accg[r][1], ad[r], bg2.y);
                fma2(accu[r][0], ad[r], bu2.x);
                fma2(accu[r][1], ad[r], bu2.y);
            }
        }
        __syncthreads();
    }
    // epilogue: silu(gate) * up
    #pragma unroll
    for (int r = 0; r < 8; r++) {
        int m = m0 + ty * 8 + r;
        if (m >= cnt) continue;
        float* hp = H + (size_t)(off + m) * IDIM + n0 + tx * 4;
        float2 gl = unpack2(accg[r][0]), gh = unpack2(accg[r][1]);
        float2 ul = unpack2(accu[r][0]), uh = unpack2(accu[r][1]);
        float4 hv;
        hv.x = gl.x / (1.f + expf(-gl.x)) * ul.x;
        hv.y = gl.y / (1.f + expf(-gl.y)) * ul.y;
        hv.z = gh.x / (1.f + expf(-gh.x)) * uh.x;
        hv.w = gh.y / (1.f + expf(-gh.y)) * uh.y;
        *(float4*)hp = hv;
    }
}

// ---------------- GEMM 2: out (+)= H @ Wd  ----------------
template<int IDIM, bool ROUTED>
__global__ void __launch_bounds__(256, 2)
gemm_down(const float* __restrict__ Wd,
          float* __restrict__ out) {
    int e   = ROUTED ? blockIdx.z : 0;
    int cnt = ROUTED ? g_counts[e]  : NT;
    int off = ROUTED ? g_offsets[e] : 0;
    int m0  = blockIdx.x * 128;
    if (m0 >= cnt) return;
    int n0  = blockIdx.y * 64;
    const float* wd = Wd + (size_t)e * IDIM * ND;
    const float* H  = ROUTED ? g_h : g_hs;

    __shared__ float2 As2[16][132];
    __shared__ float  Bs[16][68];

    int tid = threadIdx.x;
    int tx = tid & 15, ty = tid >> 4;

    const float* aptr[2];
    int mA[2], kA[2];
    #pragma unroll
    for (int l = 0; l < 2; l++) {
        int idx = tid + l * 256;
        mA[l] = idx >> 2; kA[l] = (idx & 3) << 2;
        int m = m0 + mA[l];
        int hr = (m < cnt) ? (off + m) : off;  // clamp to valid row (result discarded)
        aptr[l] = H + (size_t)hr * IDIM + kA[l];
    }
    int kB = tid >> 4, nB = (tid & 15) << 2;
    const float* bp = wd + (size_t)kB * ND + n0 + nB;

    u64 acc[8][2];
    #pragma unroll
    for (int r = 0; r < 8; r++) { acc[r][0] = 0ull; acc[r][1] = 0ull; }

    float4 ra0 = *(const float4*)(aptr[0]);
    float4 ra1 = *(const float4*)(aptr[1]);
    float4 rb  = *(const float4*)(bp);

    for (int kt = 0; kt < IDIM; kt += 16) {
        As2[kA[0]+0][mA[0]] = make_float2(ra0.x, ra0.x);
        As2[kA[0]+1][mA[0]] = make_float2(ra0.y, ra0.y);
        As2[kA[0]+2][mA[0]] = make_float2(ra0.z, ra0.z);
        As2[kA[0]+3][mA[0]] = make_float2(ra0.w, ra0.w);
        As2[kA[1]+0][mA[1]] = make_float2(ra1.x, ra1.x);
        As2[kA[1]+1][mA[1]] = make_float2(ra1.y, ra1.y);
        As2[kA[1]+2][mA[1]] = make_float2(ra1.z, ra1.z);
        As2[kA[1]+3][mA[1]] = make_float2(ra1.w, ra1.w);
        *(float4*)&Bs[kB][nB] = rb;
        __syncthreads();
        if (kt + 16 < IDIM) {
            ra0 = *(const float4*)(aptr[0] + kt + 16);
            ra1 = *(const float4*)(aptr[1] + kt + 16);
            rb  = *(const float4*)(bp + (size_t)(kt + 16) * ND);
        }
        #pragma unroll
        for (int kk = 0; kk < 16; kk++) {
            u64 ad[8];
            const ulonglong2* ap = reinterpret_cast<const ulonglong2*>(&As2[kk][ty * 8]);
            ulonglong2 p0 = ap[0], p1 = ap[1], p2 = ap[2], p3 = ap[3];
            ad[0] = p0.x; ad[1] = p0.y; ad[2] = p1.x; ad[3] = p1.y;
            ad[4] = p2.x; ad[5] = p2.y; ad[6] = p3.x; ad[7] = p3.y;
            ulonglong2 b2 = *reinterpret_cast<const ulonglong2*>(&Bs[kk][tx * 4]);
            #pragma unroll
            for (int r = 0; r < 8; r++) {
                fma2(acc[r][0], ad[r], b2.x);
                fma2(acc[r][1], ad[r], b2.y);
            }
        }
        __syncthreads();
    }
    #pragma unroll
    for (int r = 0; r < 8; r++) {
        int m = m0 + ty * 8 + r;
        if (m >= cnt) continue;
        float2 v0 = unpack2(acc[r][0]), v1 = unpack2(acc[r][1]);
        if (ROUTED) {
            int gr = off + m;
            int t  = g_rowlist[gr];
            float w = g_roww[gr] * 2.5f;   // routed scaling
            float* op = out + (size_t)t * ND + n0 + tx * 4;
            atomicAdd(&op[0], w * v0.x);
            atomicAdd(&op[1], w * v0.y);
            atomicAdd(&op[2], w * v1.x);
            atomicAdd(&op[3], w * v1.y);
        } else {
            float* op = out + (size_t)m * ND + n0 + tx * 4;
            float4 v; v.x = v0.x; v.y = v0.y; v.z = v1.x; v.w = v1.y;
            *(float4*)op = v;
        }
    }
}

// ---------------- launch ----------------
extern "C" void kernel_launch(void* const* d_in, const int* in_sizes, int n_in,
                              void* d_out, int out_size) {
    const float* x       = (const float*)d_in[0];
    const float* gate_w  = (const float*)d_in[1];
    const float* gate_b  = (const float*)d_in[2];
    const float* w_gate  = (const float*)d_in[3];
    const float* w_up    = (const float*)d_in[4];
    const float* w_down  = (const float*)d_in[5];
    const float* sw_gate = (const float*)d_in[6];
    const float* sw_up   = (const float*)d_in[7];
    const float* sw_down = (const float*)d_in[8];
    float* out = (float*)d_out;

    zero_kernel   <<<1, 32>>>();
    gate_kernel   <<<NT, 256>>>(x, gate_w, gate_b);
    scan_kernel   <<<1, 32>>>();
    scatter_kernel<<<NA / 256, 256>>>();

    // shared expert: gate/up then down (down WRITES out -> must precede routed atomics)
    gemm_gated<NSI, false><<<dim3(NT / 128, NSI / 64, 1), 256>>>(x, sw_gate, sw_up);
    // routed experts: gate/up
    gemm_gated<NI,  true ><<<dim3(NT / 128, NI  / 64, NE), 256>>>(x, w_gate, w_up);
    // shared down-proj: plain stores initialize out
    gemm_down<NSI, false><<<dim3(NT / 128, ND / 64, 1), 256>>>(sw_down, out);
    // routed down-proj: weighted atomic accumulation into out
    gemm_down<NI,  true ><<<dim3(NT / 128, ND / 64, NE), 256>>>(w_down, out);
}

// round 5
// speedup vs baseline: 1.5321x; 1.5321x over previous
#include <cuda_runtime.h>
#include <math.h>

// Problem constants
#define NT   1024          // tokens
#define ND   2048          // hidden dim
#define NE   32            // experts
#define NI   1408          // routed intermediate
#define NSI  2816          // shared intermediate
#define NG   8             // groups
#define EPG  4             // experts per group
#define NA   (NT * 4)      // total assignments (top_k = 4, exact)

// ---------------- device scratch (no allocation allowed) ----------------
__device__ float g_h [NA * NI];    // routed  silu(x@Wg)*(x@Wu)
__device__ float g_hs[NT * NSI];   // shared  silu(x@Sg)*(x@Su)
__device__ int   g_rowlist[NA];    // assignment row -> token id (grouped by expert)
__device__ float g_roww  [NA];     // assignment row -> combine weight
__device__ int   g_counts [NE];
__device__ int   g_offsets[NE];
__device__ int   g_cursor [NE];
__device__ int   g_tid4[NA];       // per-token top-4 expert ids
__device__ float g_tw4 [NA];       // per-token top-4 weights (normalized)

// ---------------- tf32 helpers ----------------
__device__ __forceinline__ unsigned f2tf32(float v) {
    unsigned r; asm("cvt.rna.tf32.f32 %0, %1;" : "=r"(r) : "f"(v)); return r;
}
__device__ __forceinline__ void cvt_split4(float4 v, uint4& h, uint4& l) {
    h.x = f2tf32(v.x); l.x = f2tf32(v.x - __uint_as_float(h.x));
    h.y = f2tf32(v.y); l.y = f2tf32(v.y - __uint_as_float(h.y));
    h.z = f2tf32(v.z); l.z = f2tf32(v.z - __uint_as_float(h.z));
    h.w = f2tf32(v.w); l.w = f2tf32(v.w - __uint_as_float(h.w));
}
// D += A(16x8 tf32) * B(8x8 tf32), fp32 accumulate
__device__ __forceinline__ void mma_tf32(float* d, const unsigned* a, const unsigned* b) {
    asm volatile(
        "mma.sync.aligned.m16n8k8.row.col.f32.tf32.tf32.f32 "
        "{%0,%1,%2,%3}, {%4,%5,%6,%7}, {%8,%9}, {%0,%1,%2,%3};"
        : "+f"(d[0]), "+f"(d[1]), "+f"(d[2]), "+f"(d[3])
        : "r"(a[0]), "r"(a[1]), "r"(a[2]), "r"(a[3]), "r"(b[0]), "r"(b[1]));
}

// ---------------- tiny kernels ----------------
__global__ void zero_kernel() {
    int i = threadIdx.x;
    if (i < NE) { g_counts[i] = 0; g_cursor[i] = 0; }
}

// One block per token: logits = x@gate_w^T + gate_b ; sigmoid ; biased grouped top-k.
__global__ void gate_kernel(const float* __restrict__ x,
                            const float* __restrict__ gw,
                            const float* __restrict__ gb) {
    __shared__ float xs[ND];
    __shared__ float logit[NE];
    int t = blockIdx.x;
    for (int k = threadIdx.x; k < ND; k += 256) xs[k] = x[(size_t)t * ND + k];
    __syncthreads();

    int e = threadIdx.x >> 3;         // 32 experts x 8 threads
    int j = threadIdx.x & 7;
    const float* w = gw + (size_t)e * ND;
    float s = 0.f;
    for (int k = j; k < ND; k += 8) s += xs[k] * w[k];
    s += __shfl_xor_sync(0xffffffffu, s, 1);
    s += __shfl_xor_sync(0xffffffffu, s, 2);
    s += __shfl_xor_sync(0xffffffffu, s, 4);
    if (j == 0) logit[e] = s + gb[e];
    __syncthreads();

    if (threadIdx.x == 0) {
        float sc[NE], scb[NE];
        #pragma unroll
        for (int i = 0; i < NE; i++) {
            float v = 1.f / (1.f + expf(-logit[i]));
            sc[i]  = v;             // unbiased sigmoid (used for weights)
            scb[i] = v + gb[i];     // biased score (used for choice)
        }
        // group score = sum of top-2 biased scores in each group of 4
        float gs[NG];
        #pragma unroll
        for (int g = 0; g < NG; g++) {
            float m1 = -1e30f, m2 = -1e30f;
            #pragma unroll
            for (int q = 0; q < EPG; q++) {
                float v = scb[g * EPG + q];
                if (v > m1) { m2 = m1; m1 = v; } else if (v > m2) { m2 = v; }
            }
            gs[g] = m1 + m2;
        }
        // top-4 groups (strict '>' scan in ascending index order == lax.top_k tie rule)
        bool gsel[NG];
        #pragma unroll
        for (int g = 0; g < NG; g++) gsel[g] = false;
        for (int r = 0; r < 4; r++) {
            float best = -1e30f; int bi = 0;
            for (int g = 0; g < NG; g++)
                if (!gsel[g] && gs[g] > best) { best = gs[g]; bi = g; }
            gsel[bi] = true;
        }
        // masked scores: exactly jnp.where(mask, scb, 0.0)
        float tmp[NE];
        #pragma unroll
        for (int i = 0; i < NE; i++) tmp[i] = gsel[i / EPG] ? scb[i] : 0.0f;
        // top-4 experts of tmp
        int ids[4]; float tw[4]; float wsum = 0.f;
        for (int r = 0; r < 4; r++) {
            float best = -1e30f; int bi = 0;
            for (int i = 0; i < NE; i++)
                if (tmp[i] > best) { best = tmp[i]; bi = i; }
            tmp[bi] = -1e30f;
            ids[r] = bi;
            tw[r] = sc[bi];           // weights from UNbiased sigmoid scores
            wsum += tw[r];
        }
        float inv = 1.f / wsum;
        for (int r = 0; r < 4; r++) {
            g_tid4[t * 4 + r] = ids[r];
            g_tw4 [t * 4 + r] = tw[r] * inv;
            atomicAdd(&g_counts[ids[r]], 1);
        }
    }
}

__global__ void scan_kernel() {   // 32 threads: exclusive scan of counts
    int tid = threadIdx.x;
    int c = g_counts[tid];
    int v = c;
    #pragma unroll
    for (int o = 1; o < 32; o <<= 1) {
        int u = __shfl_up_sync(0xffffffffu, v, o);
        if (tid >= o) v += u;
    }
    g_offsets[tid] = v - c;
}

__global__ void scatter_kernel() {
    int i = blockIdx.x * blockDim.x + threadIdx.x;
    if (i >= NA) return;
    int t = i >> 2;
    int e = g_tid4[i];
    int pos = atomicAdd(&g_cursor[e], 1);
    int row = g_offsets[e] + pos;
    g_rowlist[row] = t;
    g_roww[row]   = g_tw4[i];
}

// ============================================================================
// Tensor-core GEMMs: 3xTF32 split (a_hi*b_hi + a_hi*b_lo + a_lo*b_hi).
// Block: BM=128, BN=64, BK=16, 256 threads = 8 warps, warp tile 32x32,
// mma.m16n8k8: per warp 2 m-tiles x 4 n-tiles.
// SMEM: A in [m][20] (stride 20 -> conflict-free frag loads & ST.128),
//       B in [k][72] (stride 72 == 8 mod 32 -> conflict-free frag loads).
// ============================================================================

#define A_STR 20
#define B_STR 72

// ---------------- GEMM 1: H = silu(A@Wg) * (A@Wu) ----------------
template<int IDIM, bool GATHER>
__global__ void __launch_bounds__(256, 2)
gemm_gated(const float* __restrict__ x,
           const float* __restrict__ Wg,
           const float* __restrict__ Wu) {
    int e   = GATHER ? blockIdx.z : 0;
    int cnt = GATHER ? g_counts[e]  : NT;
    int off = GATHER ? g_offsets[e] : 0;
    int m0  = blockIdx.x * 128;
    if (m0 >= cnt) return;
    int n0  = blockIdx.y * 64;
    const float* wg = Wg + (size_t)e * ND * IDIM;
    const float* wu = Wu + (size_t)e * ND * IDIM;
    float* H = GATHER ? g_h : g_hs;

    __shared__ unsigned Ah[128 * A_STR], Al[128 * A_STR];
    __shared__ unsigned Bgh[16 * B_STR], Bgl[16 * B_STR];
    __shared__ unsigned Buh[16 * B_STR], Bul[16 * B_STR];

    int tid  = threadIdx.x;
    int lane = tid & 31, wid = tid >> 5;
    int warpM = wid >> 1, warpN = wid & 1;   // 4 x 2 warps
    int gq = lane >> 2, tq = lane & 3;       // groupID / threadID_in_group

    // A loader: two float4 per thread
    const float* aptr[2]; int mA[2], kA[2];
    #pragma unroll
    for (int l = 0; l < 2; l++) {
        int idx = tid + l * 256;
        mA[l] = idx >> 2; kA[l] = (idx & 3) << 2;
        int m = m0 + mA[l];
        int tok;
        if (GATHER) tok = (m < cnt) ? g_rowlist[off + m] : 0;
        else        tok = (m < cnt) ? m : 0;
        aptr[l] = x + (size_t)tok * ND + kA[l];
    }
    // B loader: one float4 per thread per matrix
    int kB = tid >> 4, nB = (tid & 15) << 2;
    const float* bgp = wg + (size_t)kB * IDIM + n0 + nB;
    const float* bup = wu + (size_t)kB * IDIM + n0 + nB;

    float accg[2][4][4], accu[2][4][4];
    #pragma unroll
    for (int mt = 0; mt < 2; mt++)
        #pragma unroll
        for (int nt = 0; nt < 4; nt++)
            #pragma unroll
            for (int r = 0; r < 4; r++) { accg[mt][nt][r] = 0.f; accu[mt][nt][r] = 0.f; }

    float4 ra0 = *(const float4*)(aptr[0]);
    float4 ra1 = *(const float4*)(aptr[1]);
    float4 rbg = *(const float4*)(bgp);
    float4 rbu = *(const float4*)(bup);

    for (int kt = 0; kt < ND; kt += 16) {
        uint4 h, l;
        cvt_split4(ra0, h, l);
        *(uint4*)&Ah[mA[0] * A_STR + kA[0]] = h;
        *(uint4*)&Al[mA[0] * A_STR + kA[0]] = l;
        cvt_split4(ra1, h, l);
        *(uint4*)&Ah[mA[1] * A_STR + kA[1]] = h;
        *(uint4*)&Al[mA[1] * A_STR + kA[1]] = l;
        cvt_split4(rbg, h, l);
        *(uint4*)&Bgh[kB * B_STR + nB] = h;
        *(uint4*)&Bgl[kB * B_STR + nB] = l;
        cvt_split4(rbu, h, l);
        *(uint4*)&Buh[kB * B_STR + nB] = h;
        *(uint4*)&Bul[kB * B_STR + nB] = l;
        __syncthreads();
        if (kt + 16 < ND) {
            ra0 = *(const float4*)(aptr[0] + kt + 16);
            ra1 = *(const float4*)(aptr[1] + kt + 16);
            rbg = *(const float4*)(bgp + (size_t)(kt + 16) * IDIM);
            rbu = *(const float4*)(bup + (size_t)(kt + 16) * IDIM);
        }
        #pragma unroll
        for (int ks = 0; ks < 2; ks++) {
            int kk = ks * 8 + tq;
            unsigned ah[2][4], al[2][4];
            #pragma unroll
            for (int mt = 0; mt < 2; mt++) {
                int r = warpM * 32 + mt * 16 + gq;
                ah[mt][0] = Ah[r * A_STR + kk];
                ah[mt][1] = Ah[(r + 8) * A_STR + kk];
                ah[mt][2] = Ah[r * A_STR + kk + 4];
                ah[mt][3] = Ah[(r + 8) * A_STR + kk + 4];
                al[mt][0] = Al[r * A_STR + kk];
                al[mt][1] = Al[(r + 8) * A_STR + kk];
                al[mt][2] = Al[r * A_STR + kk + 4];
                al[mt][3] = Al[(r + 8) * A_STR + kk + 4];
            }
            unsigned bf[4][2];
            // gate: hi*hi + lo*hi
            #pragma unroll
            for (int nt = 0; nt < 4; nt++) {
                int c = warpN * 32 + nt * 8 + gq;
                bf[nt][0] = Bgh[kk * B_STR + c];
                bf[nt][1] = Bgh[(kk + 4) * B_STR + c];
            }
            #pragma unroll
            for (int mt = 0; mt < 2; mt++)
                #pragma unroll
                for (int nt = 0; nt < 4; nt++) {
                    mma_tf32(accg[mt][nt], ah[mt], bf[nt]);
                    mma_tf32(accg[mt][nt], al[mt], bf[nt]);
                }
            // gate: hi*lo
            #pragma unroll
            for (int nt = 0; nt < 4; nt++) {
                int c = warpN * 32 + nt * 8 + gq;
                bf[nt][0] = Bgl[kk * B_STR + c];
                bf[nt][1] = Bgl[(kk + 4) * B_STR + c];
            }
            #pragma unroll
            for (int mt = 0; mt < 2; mt++)
                #pragma unroll
                for (int nt = 0; nt < 4; nt++)
                    mma_tf32(accg[mt][nt], ah[mt], bf[nt]);
            // up: hi*hi + lo*hi
            #pragma unroll
            for (int nt = 0; nt < 4; nt++) {
                int c = warpN * 32 + nt * 8 + gq;
                bf[nt][0] = Buh[kk * B_STR + c];
                bf[nt][1] = Buh[(kk + 4) * B_STR + c];
            }
            #pragma unroll
            for (int mt = 0; mt < 2; mt++)
                #pragma unroll
                for (int nt = 0; nt < 4; nt++) {
                    mma_tf32(accu[mt][nt], ah[mt], bf[nt]);
                    mma_tf32(accu[mt][nt], al[mt], bf[nt]);
                }
            // up: hi*lo
            #pragma unroll
            for (int nt = 0; nt < 4; nt++) {
                int c = warpN * 32 + nt * 8 + gq;
                bf[nt][0] = Bul[kk * B_STR + c];
                bf[nt][1] = Bul[(kk + 4) * B_STR + c];
            }
            #pragma unroll
            for (int mt = 0; mt < 2; mt++)
                #pragma unroll
                for (int nt = 0; nt < 4; nt++)
                    mma_tf32(accu[mt][nt], ah[mt], bf[nt]);
        }
        __syncthreads();
    }
    // epilogue: silu(gate) * up
    #pragma unroll
    for (int mt = 0; mt < 2; mt++) {
        #pragma unroll
        for (int half = 0; half < 2; half++) {
            int r = m0 + warpM * 32 + mt * 16 + half * 8 + gq;
            if (r >= cnt) continue;
            float* hrow = H + (size_t)(off + r) * IDIM + n0 + warpN * 32;
            #pragma unroll
            for (int nt = 0; nt < 4; nt++) {
                float gv0 = accg[mt][nt][half * 2 + 0];
                float gv1 = accg[mt][nt][half * 2 + 1];
                float uv0 = accu[mt][nt][half * 2 + 0];
                float uv1 = accu[mt][nt][half * 2 + 1];
                float2 hv;
                hv.x = gv0 / (1.f + expf(-gv0)) * uv0;
                hv.y = gv1 / (1.f + expf(-gv1)) * uv1;
                *(float2*)&hrow[nt * 8 + 2 * tq] = hv;
            }
        }
    }
}

// ---------------- GEMM 2: out (+)= H @ Wd  ----------------
template<int IDIM, bool ROUTED>
__global__ void __launch_bounds__(256, 2)
gemm_down(const float* __restrict__ Wd,
          float* __restrict__ out) {
    int e   = ROUTED ? blockIdx.z : 0;
    int cnt = ROUTED ? g_counts[e]  : NT;
    int off = ROUTED ? g_offsets[e] : 0;
    int m0  = blockIdx.x * 128;
    if (m0 >= cnt) return;
    int n0  = blockIdx.y * 64;
    const float* wd = Wd + (size_t)e * IDIM * ND;
    const float* H  = ROUTED ? g_h : g_hs;

    __shared__ unsigned Ah[128 * A_STR], Al[128 * A_STR];
    __shared__ unsigned Bh[16 * B_STR], Bl[16 * B_STR];

    int tid  = threadIdx.x;
    int lane = tid & 31, wid = tid >> 5;
    int warpM = wid >> 1, warpN = wid & 1;
    int gq = lane >> 2, tq = lane & 3;

    const float* aptr[2]; int mA[2], kA[2];
    #pragma unroll
    for (int l = 0; l < 2; l++) {
        int idx = tid + l * 256;
        mA[l] = idx >> 2; kA[l] = (idx & 3) << 2;
        int m = m0 + mA[l];
        int hr = (m < cnt) ? (off + m) : off;  // clamp to valid row (result discarded)
        aptr[l] = H + (size_t)hr * IDIM + kA[l];
    }
    int kB = tid >> 4, nB = (tid & 15) << 2;
    const float* bp = wd + (size_t)kB * ND + n0 + nB;

    float acc[2][4][4];
    #pragma unroll
    for (int mt = 0; mt < 2; mt++)
        #pragma unroll
        for (int nt = 0; nt < 4; nt++)
            #pragma unroll
            for (int r = 0; r < 4; r++) acc[mt][nt][r] = 0.f;

    float4 ra0 = *(const float4*)(aptr[0]);
    float4 ra1 = *(const float4*)(aptr[1]);
    float4 rb  = *(const float4*)(bp);

    for (int kt = 0; kt < IDIM; kt += 16) {
        uint4 h, l;
        cvt_split4(ra0, h, l);
        *(uint4*)&Ah[mA[0] * A_STR + kA[0]] = h;
        *(uint4*)&Al[mA[0] * A_STR + kA[0]] = l;
        cvt_split4(ra1, h, l);
        *(uint4*)&Ah[mA[1] * A_STR + kA[1]] = h;
        *(uint4*)&Al[mA[1] * A_STR + kA[1]] = l;
        cvt_split4(rb, h, l);
        *(uint4*)&Bh[kB * B_STR + nB] = h;
        *(uint4*)&Bl[kB * B_STR + nB] = l;
        __syncthreads();
        if (kt + 16 < IDIM) {
            ra0 = *(const float4*)(aptr[0] + kt + 16);
            ra1 = *(const float4*)(aptr[1] + kt + 16);
            rb  = *(const float4*)(bp + (size_t)(kt + 16) * ND);
        }
        #pragma unroll
        for (int ks = 0; ks < 2; ks++) {
            int kk = ks * 8 + tq;
            unsigned ah[2][4], al[2][4];
            #pragma unroll
            for (int mt = 0; mt < 2; mt++) {
                int r = warpM * 32 + mt * 16 + gq;
                ah[mt][0] = Ah[r * A_STR + kk];
                ah[mt][1] = Ah[(r + 8) * A_STR + kk];
                ah[mt][2] = Ah[r * A_STR + kk + 4];
                ah[mt][3] = Ah[(r + 8) * A_STR + kk + 4];
                al[mt][0] = Al[r * A_STR + kk];
                al[mt][1] = Al[(r + 8) * A_STR + kk];
                al[mt][2] = Al[r * A_STR + kk + 4];
                al[mt][3] = Al[(r + 8) * A_STR + kk + 4];
            }
            unsigned bf[4][2];
            // hi*hi + lo*hi
            #pragma unroll
            for (int nt = 0; nt < 4; nt++) {
                int c = warpN * 32 + nt * 8 + gq;
                bf[nt][0] = Bh[kk * B_STR + c];
                bf[nt][1] = Bh[(kk + 4) * B_STR + c];
            }
            #pragma unroll
            for (int mt = 0; mt < 2; mt++)
                #pragma unroll
                for (int nt = 0; nt < 4; nt++) {
                    mma_tf32(acc[mt][nt], ah[mt], bf[nt]);
                    mma_tf32(acc[mt][nt], al[mt], bf[nt]);
                }
            // hi*lo
            #pragma unroll
            for (int nt = 0; nt < 4; nt++) {
                int c = warpN * 32 + nt * 8 + gq;
                bf[nt][0] = Bl[kk * B_STR + c];
                bf[nt][1] = Bl[(kk + 4) * B_STR + c];
            }
            #pragma unroll
            for (int mt = 0; mt < 2; mt++)
                #pragma unroll
                for (int nt = 0; nt < 4; nt++)
                    mma_tf32(acc[mt][nt], ah[mt], bf[nt]);
        }
        __syncthreads();
    }
    // epilogue
    #pragma unroll
    for (int mt = 0; mt < 2; mt++) {
        #pragma unroll
        for (int half = 0; half < 2; half++) {
            int r = m0 + warpM * 32 + mt * 16 + half * 8 + gq;
            if (r >= cnt) continue;
            if (ROUTED) {
                int grow = off + r;
                int tok  = g_rowlist[grow];
                float w  = g_roww[grow] * 2.5f;   // routed scaling
                float* op = out + (size_t)tok * ND + n0 + warpN * 32;
                #pragma unroll
                for (int nt = 0; nt < 4; nt++) {
                    atomicAdd(&op[nt * 8 + 2 * tq],     w * acc[mt][nt][half * 2 + 0]);
                    atomicAdd(&op[nt * 8 + 2 * tq + 1], w * acc[mt][nt][half * 2 + 1]);
                }
            } else {
                float* op = out + (size_t)r * ND + n0 + warpN * 32;
                #pragma unroll
                for (int nt = 0; nt < 4; nt++) {
                    float2 v;
                    v.x = acc[mt][nt][half * 2 + 0];
                    v.y = acc[mt][nt][half * 2 + 1];
                    *(float2*)&op[nt * 8 + 2 * tq] = v;
                }
            }
        }
    }
}

// ---------------- launch ----------------
extern "C" void kernel_launch(void* const* d_in, const int* in_sizes, int n_in,
                              void* d_out, int out_size) {
    const float* x       = (const float*)d_in[0];
    const float* gate_w  = (const float*)d_in[1];
    const float* gate_b  = (const float*)d_in[2];
    const float* w_gate  = (const float*)d_in[3];
    const float* w_up    = (const float*)d_in[4];
    const float* w_down  = (const float*)d_in[5];
    const float* sw_gate = (const float*)d_in[6];
    const float* sw_up   = (const float*)d_in[7];
    const float* sw_down = (const float*)d_in[8];
    float* out = (float*)d_out;

    zero_kernel   <<<1, 32>>>();
    gate_kernel   <<<NT, 256>>>(x, gate_w, gate_b);
    scan_kernel   <<<1, 32>>>();
    scatter_kernel<<<NA / 256, 256>>>();

    // shared expert: gate/up then down (down WRITES out -> must precede routed atomics)
    gemm_gated<NSI, false><<<dim3(NT / 128, NSI / 64, 1), 256>>>(x, sw_gate, sw_up);
    // routed experts: gate/up
    gemm_gated<NI,  true ><<<dim3(NT / 128, NI  / 64, NE), 256>>>(x, w_gate, w_up);
    // shared down-proj: plain stores initialize out
    gemm_down<NSI, false><<<dim3(NT / 128, ND / 64, 1), 256>>>(sw_down, out);
    // routed down-proj: weighted atomic accumulation into out
    gemm_down<NI,  true ><<<dim3(NT / 128, ND / 64, NE), 256>>>(w_down, out);
}

// round 6
// speedup vs baseline: 2.0583x; 1.3435x over previous
#include <cuda_runtime.h>
#include <cuda_bf16.h>
#include <math.h>

// Problem constants
#define NT   1024          // tokens
#define ND   2048          // hidden dim
#define NE   32            // experts
#define NI   1408          // routed intermediate
#define NSI  2816          // shared intermediate
#define NG   8             // groups
#define EPG  4             // experts per group
#define NA   (NT * 4)      // total assignments (top_k = 4, exact)

// ---------------- device scratch (no allocation allowed) ----------------
__device__ float g_h [NA * NI];    // routed  silu(x@Wg)*(x@Wu)
__device__ float g_hs[NT * NSI];   // shared  silu(x@Sg)*(x@Su)
__device__ int   g_rowlist[NA];    // assignment row -> token id (grouped by expert)
__device__ float g_roww  [NA];     // assignment row -> combine weight
__device__ int   g_counts [NE];
__device__ int   g_offsets[NE];
__device__ int   g_cursor [NE];
__device__ int   g_tid4[NA];       // per-token top-4 expert ids
__device__ float g_tw4 [NA];       // per-token top-4 weights (normalized)

// ---------------- bf16 split helpers ----------------
// v = hi + lo (bf16 each); pack two consecutive-k values into one u32 (low = even k).
__device__ __forceinline__ void split2(float v0, float v1, unsigned& h, unsigned& l) {
    __nv_bfloat16 h0 = __float2bfloat16_rn(v0);
    __nv_bfloat16 h1 = __float2bfloat16_rn(v1);
    float r0 = v0 - __bfloat162float(h0);
    float r1 = v1 - __bfloat162float(h1);
    __nv_bfloat16 l0 = __float2bfloat16_rn(r0);
    __nv_bfloat16 l1 = __float2bfloat16_rn(r1);
    h = (unsigned)*(unsigned short*)&h0 | ((unsigned)*(unsigned short*)&h1 << 16);
    l = (unsigned)*(unsigned short*)&l0 | ((unsigned)*(unsigned short*)&l1 << 16);
}

// D += A(16x16 bf16) * B(16x8 bf16), fp32 accumulate
__device__ __forceinline__ void mma_bf16(float* d, const unsigned* a, const unsigned* b) {
    asm volatile(
        "mma.sync.aligned.m16n8k16.row.col.f32.bf16.bf16.f32 "
        "{%0,%1,%2,%3}, {%4,%5,%6,%7}, {%8,%9}, {%0,%1,%2,%3};"
        : "+f"(d[0]), "+f"(d[1]), "+f"(d[2]), "+f"(d[3])
        : "r"(a[0]), "r"(a[1]), "r"(a[2]), "r"(a[3]), "r"(b[0]), "r"(b[1]));
}

// ---------------- tiny kernels ----------------
__global__ void zero_kernel() {
    int i = threadIdx.x;
    if (i < NE) { g_counts[i] = 0; g_cursor[i] = 0; }
}

// One block per token: logits = x@gate_w^T + gate_b ; sigmoid ; biased grouped top-k.
__global__ void gate_kernel(const float* __restrict__ x,
                            const float* __restrict__ gw,
                            const float* __restrict__ gb) {
    __shared__ float xs[ND];
    __shared__ float logit[NE];
    int t = blockIdx.x;
    for (int k = threadIdx.x; k < ND; k += 256) xs[k] = x[(size_t)t * ND + k];
    __syncthreads();

    int e = threadIdx.x >> 3;         // 32 experts x 8 threads
    int j = threadIdx.x & 7;
    const float* w = gw + (size_t)e * ND;
    float s = 0.f;
    for (int k = j; k < ND; k += 8) s += xs[k] * w[k];
    s += __shfl_xor_sync(0xffffffffu, s, 1);
    s += __shfl_xor_sync(0xffffffffu, s, 2);
    s += __shfl_xor_sync(0xffffffffu, s, 4);
    if (j == 0) logit[e] = s + gb[e];
    __syncthreads();

    if (threadIdx.x == 0) {
        float sc[NE], scb[NE];
        #pragma unroll
        for (int i = 0; i < NE; i++) {
            float v = 1.f / (1.f + expf(-logit[i]));
            sc[i]  = v;             // unbiased sigmoid (used for weights)
            scb[i] = v + gb[i];     // biased score (used for choice)
        }
        // group score = sum of top-2 biased scores in each group of 4
        float gs[NG];
        #pragma unroll
        for (int g = 0; g < NG; g++) {
            float m1 = -1e30f, m2 = -1e30f;
            #pragma unroll
            for (int q = 0; q < EPG; q++) {
                float v = scb[g * EPG + q];
                if (v > m1) { m2 = m1; m1 = v; } else if (v > m2) { m2 = v; }
            }
            gs[g] = m1 + m2;
        }
        // top-4 groups (strict '>' scan in ascending index order == lax.top_k tie rule)
        bool gsel[NG];
        #pragma unroll
        for (int g = 0; g < NG; g++) gsel[g] = false;
        for (int r = 0; r < 4; r++) {
            float best = -1e30f; int bi = 0;
            for (int g = 0; g < NG; g++)
                if (!gsel[g] && gs[g] > best) { best = gs[g]; bi = g; }
            gsel[bi] = true;
        }
        // masked scores: exactly jnp.where(mask, scb, 0.0)
        float tmp[NE];
        #pragma unroll
        for (int i = 0; i < NE; i++) tmp[i] = gsel[i / EPG] ? scb[i] : 0.0f;
        // top-4 experts of tmp
        int ids[4]; float tw[4]; float wsum = 0.f;
        for (int r = 0; r < 4; r++) {
            float best = -1e30f; int bi = 0;
            for (int i = 0; i < NE; i++)
                if (tmp[i] > best) { best = tmp[i]; bi = i; }
            tmp[bi] = -1e30f;
            ids[r] = bi;
            tw[r] = sc[bi];           // weights from UNbiased sigmoid scores
            wsum += tw[r];
        }
        float inv = 1.f / wsum;
        for (int r = 0; r < 4; r++) {
            g_tid4[t * 4 + r] = ids[r];
            g_tw4 [t * 4 + r] = tw[r] * inv;
            atomicAdd(&g_counts[ids[r]], 1);
        }
    }
}

__global__ void scan_kernel() {   // 32 threads: exclusive scan of counts
    int tid = threadIdx.x;
    int c = g_counts[tid];
    int v = c;
    #pragma unroll
    for (int o = 1; o < 32; o <<= 1) {
        int u = __shfl_up_sync(0xffffffffu, v, o);
        if (tid >= o) v += u;
    }
    g_offsets[tid] = v - c;
}

__global__ void scatter_kernel() {
    int i = blockIdx.x * blockDim.x + threadIdx.x;
    if (i >= NA) return;
    int t = i >> 2;
    int e = g_tid4[i];
    int pos = atomicAdd(&g_cursor[e], 1);
    int row = g_offsets[e] + pos;
    g_rowlist[row] = t;
    g_roww[row]   = g_tw4[i];
}

// ============================================================================
// Tensor-core GEMMs via bf16x3 emulation (hi*hi + lo*hi + hi*lo), fp32 accum.
// mma.m16n8k16.bf16. Block: BM=128, BN=64, BK=16, 256 threads = 8 warps
// (4 along M x 2 along N), warp tile 32x32 (2 m-tiles x 4 n-tiles).
// SMEM (k-paired u32):
//   A: [128 rows][8 u32], XOR swizzle col c -> c ^ (row & 7). Conflict-free
//      for both the frag loads (a0..a3) and the paired STS.
//   B: [8 kp][72 u32] (stride 72 == 8 mod 32 -> conflict-free frag loads).
// ============================================================================

#define B_STR 72

// ---------------- GEMM 1: H = silu(A@Wg) * (A@Wu) ----------------
template<int IDIM, bool GATHER>
__global__ void __launch_bounds__(256, 2)
gemm_gated(const float* __restrict__ x,
           const float* __restrict__ Wg,
           const float* __restrict__ Wu) {
    int e   = GATHER ? blockIdx.z : 0;
    int cnt = GATHER ? g_counts[e]  : NT;
    int off = GATHER ? g_offsets[e] : 0;
    int m0  = blockIdx.x * 128;
    if (m0 >= cnt) return;
    int n0  = blockIdx.y * 64;
    const float* wg = Wg + (size_t)e * ND * IDIM;
    const float* wu = Wu + (size_t)e * ND * IDIM;
    float* H = GATHER ? g_h : g_hs;

    __shared__ unsigned Ah[128 * 8], Al[128 * 8];
    __shared__ unsigned Bgh[8 * B_STR], Bgl[8 * B_STR];
    __shared__ unsigned Buh[8 * B_STR], Bul[8 * B_STR];

    int tid  = threadIdx.x;
    int lane = tid & 31, wid = tid >> 5;
    int warpM = wid >> 1, warpN = wid & 1;   // 4 x 2 warps
    int gq = lane >> 2, tq = lane & 3;       // groupID / threadID_in_group

    // A loader: two float4 per thread (covers 128x16 fp32)
    const float* aptr[2]; int mA[2], kA[2];
    #pragma unroll
    for (int l = 0; l < 2; l++) {
        int idx = tid + l * 256;
        mA[l] = idx >> 2; kA[l] = (idx & 3) << 2;
        int m = m0 + mA[l];
        int tok;
        if (GATHER) tok = (m < cnt) ? g_rowlist[off + m] : 0;
        else        tok = (m < cnt) ? m : 0;
        aptr[l] = x + (size_t)tok * ND + kA[l];
    }
    // B loader: 128 threads per matrix; thread owns (kp, 4 n-cols), loads 2 k-rows.
    int mat = tid >> 7;
    int rr  = tid & 127;
    int kpw = rr >> 4;
    int nq  = (rr & 15) << 2;
    const float* wsel = mat ? wu : wg;
    unsigned* BH = mat ? Buh : Bgh;
    unsigned* BL = mat ? Bul : Bgl;
    const float* bp = wsel + (size_t)(2 * kpw) * IDIM + n0 + nq;

    float accg[2][4][4], accu[2][4][4];
    #pragma unroll
    for (int mt = 0; mt < 2; mt++)
        #pragma unroll
        for (int nt = 0; nt < 4; nt++)
            #pragma unroll
            for (int r = 0; r < 4; r++) { accg[mt][nt][r] = 0.f; accu[mt][nt][r] = 0.f; }

    float4 ra0 = *(const float4*)(aptr[0]);
    float4 ra1 = *(const float4*)(aptr[1]);
    float4 rb0 = *(const float4*)(bp);
    float4 rb1 = *(const float4*)(bp + IDIM);

    for (int kt = 0; kt < ND; kt += 16) {
        // ---- store A (k-paired, swizzled) ----
        {
            unsigned h0, l0, h1, l1;
            int r = mA[0], cb = kA[0] >> 1, s = r & 7;
            split2(ra0.x, ra0.y, h0, l0);
            split2(ra0.z, ra0.w, h1, l1);
            Ah[r * 8 + (cb ^ s)]       = h0;
            Ah[r * 8 + ((cb + 1) ^ s)] = h1;
            Al[r * 8 + (cb ^ s)]       = l0;
            Al[r * 8 + ((cb + 1) ^ s)] = l1;
            r = mA[1]; cb = kA[1] >> 1; s = r & 7;
            split2(ra1.x, ra1.y, h0, l0);
            split2(ra1.z, ra1.w, h1, l1);
            Ah[r * 8 + (cb ^ s)]       = h0;
            Ah[r * 8 + ((cb + 1) ^ s)] = h1;
            Al[r * 8 + (cb ^ s)]       = l0;
            Al[r * 8 + ((cb + 1) ^ s)] = l1;
        }
        // ---- store B (k-paired) ----
        {
            unsigned h0, l0, h1, l1, h2, l2, h3, l3;
            split2(rb0.x, rb1.x, h0, l0);
            split2(rb0.y, rb1.y, h1, l1);
            split2(rb0.z, rb1.z, h2, l2);
            split2(rb0.w, rb1.w, h3, l3);
            *(uint4*)&BH[kpw * B_STR + nq] = make_uint4(h0, h1, h2, h3);
            *(uint4*)&BL[kpw * B_STR + nq] = make_uint4(l0, l1, l2, l3);
        }
        __syncthreads();
        if (kt + 16 < ND) {
            ra0 = *(const float4*)(aptr[0] + kt + 16);
            ra1 = *(const float4*)(aptr[1] + kt + 16);
            rb0 = *(const float4*)(bp + (size_t)(kt + 16) * IDIM);
            rb1 = *(const float4*)(bp + (size_t)(kt + 16 + 1) * IDIM - IDIM + IDIM + IDIM - IDIM);
            rb1 = *(const float4*)(bp + (size_t)(kt + 17) * IDIM);
        }
        // ---- fragments + mma ----
        {
            unsigned ah[2][4], al[2][4];
            #pragma unroll
            for (int mt = 0; mt < 2; mt++) {
                int R = warpM * 32 + mt * 16 + gq;
                int base = R * 8;
                int c0 = tq ^ gq, c1 = (tq + 4) ^ gq;
                ah[mt][0] = Ah[base + c0];
                ah[mt][1] = Ah[base + 64 + c0];
                ah[mt][2] = Ah[base + c1];
                ah[mt][3] = Ah[base + 64 + c1];
                al[mt][0] = Al[base + c0];
                al[mt][1] = Al[base + 64 + c0];
                al[mt][2] = Al[base + c1];
                al[mt][3] = Al[base + 64 + c1];
            }
            #pragma unroll
            for (int nt = 0; nt < 4; nt++) {
                int c = warpN * 32 + nt * 8 + gq;
                unsigned bgh[2], bgl[2], buh[2], bul[2];
                bgh[0] = Bgh[tq * B_STR + c]; bgh[1] = Bgh[(tq + 4) * B_STR + c];
                bgl[0] = Bgl[tq * B_STR + c]; bgl[1] = Bgl[(tq + 4) * B_STR + c];
                buh[0] = Buh[tq * B_STR + c]; buh[1] = Buh[(tq + 4) * B_STR + c];
                bul[0] = Bul[tq * B_STR + c]; bul[1] = Bul[(tq + 4) * B_STR + c];
                #pragma unroll
                for (int mt = 0; mt < 2; mt++) {
                    mma_bf16(accg[mt][nt], ah[mt], bgh);
                    mma_bf16(accg[mt][nt], al[mt], bgh);
                    mma_bf16(accg[mt][nt], ah[mt], bgl);
                    mma_bf16(accu[mt][nt], ah[mt], buh);
                    mma_bf16(accu[mt][nt], al[mt], buh);
                    mma_bf16(accu[mt][nt], ah[mt], bul);
                }
            }
        }
        __syncthreads();
    }
    // epilogue: silu(gate) * up
    #pragma unroll
    for (int mt = 0; mt < 2; mt++) {
        #pragma unroll
        for (int half = 0; half < 2; half++) {
            int r = m0 + warpM * 32 + mt * 16 + half * 8 + gq;
            if (r >= cnt) continue;
            float* hrow = H + (size_t)(off + r) * IDIM + n0 + warpN * 32;
            #pragma unroll
            for (int nt = 0; nt < 4; nt++) {
                float gv0 = accg[mt][nt][half * 2 + 0];
                float gv1 = accg[mt][nt][half * 2 + 1];
                float uv0 = accu[mt][nt][half * 2 + 0];
                float uv1 = accu[mt][nt][half * 2 + 1];
                float2 hv;
                hv.x = gv0 / (1.f + expf(-gv0)) * uv0;
                hv.y = gv1 / (1.f + expf(-gv1)) * uv1;
                *(float2*)&hrow[nt * 8 + 2 * tq] = hv;
            }
        }
    }
}

// ---------------- GEMM 2: out (+)= H @ Wd  ----------------
template<int IDIM, bool ROUTED>
__global__ void __launch_bounds__(256, 2)
gemm_down(const float* __restrict__ Wd,
          float* __restrict__ out) {
    int e   = ROUTED ? blockIdx.z : 0;
    int cnt = ROUTED ? g_counts[e]  : NT;
    int off = ROUTED ? g_offsets[e] : 0;
    int m0  = blockIdx.x * 128;
    if (m0 >= cnt) return;
    int n0  = blockIdx.y * 64;
    const float* wd = Wd + (size_t)e * IDIM * ND;
    const float* H  = ROUTED ? g_h : g_hs;

    __shared__ unsigned Ah[128 * 8], Al[128 * 8];
    __shared__ unsigned Bh[8 * B_STR], Bl[8 * B_STR];

    int tid  = threadIdx.x;
    int lane = tid & 31, wid = tid >> 5;
    int warpM = wid >> 1, warpN = wid & 1;
    int gq = lane >> 2, tq = lane & 3;

    const float* aptr[2]; int mA[2], kA[2];
    #pragma unroll
    for (int l = 0; l < 2; l++) {
        int idx = tid + l * 256;
        mA[l] = idx >> 2; kA[l] = (idx & 3) << 2;
        int m = m0 + mA[l];
        int hr = (m < cnt) ? (off + m) : off;  // clamp to valid row (result discarded)
        aptr[l] = H + (size_t)hr * IDIM + kA[l];
    }
    // B loader: first 128 threads
    int bact = (tid < 128);
    int kpw = (tid & 127) >> 4;
    int nq  = (tid & 15) << 2;
    const float* bp = wd + (size_t)(2 * kpw) * ND + n0 + nq;

    float acc[2][4][4];
    #pragma unroll
    for (int mt = 0; mt < 2; mt++)
        #pragma unroll
        for (int nt = 0; nt < 4; nt++)
            #pragma unroll
            for (int r = 0; r < 4; r++) acc[mt][nt][r] = 0.f;

    float4 ra0 = *(const float4*)(aptr[0]);
    float4 ra1 = *(const float4*)(aptr[1]);
    float4 rb0, rb1;
    if (bact) { rb0 = *(const float4*)(bp); rb1 = *(const float4*)(bp + ND); }

    for (int kt = 0; kt < IDIM; kt += 16) {
        {
            unsigned h0, l0, h1, l1;
            int r = mA[0], cb = kA[0] >> 1, s = r & 7;
            split2(ra0.x, ra0.y, h0, l0);
            split2(ra0.z, ra0.w, h1, l1);
            Ah[r * 8 + (cb ^ s)]       = h0;
            Ah[r * 8 + ((cb + 1) ^ s)] = h1;
            Al[r * 8 + (cb ^ s)]       = l0;
            Al[r * 8 + ((cb + 1) ^ s)] = l1;
            r = mA[1]; cb = kA[1] >> 1; s = r & 7;
            split2(ra1.x, ra1.y, h0, l0);
            split2(ra1.z, ra1.w, h1, l1);
            Ah[r * 8 + (cb ^ s)]       = h0;
            Ah[r * 8 + ((cb + 1) ^ s)] = h1;
            Al[r * 8 + (cb ^ s)]       = l0;
            Al[r * 8 + ((cb + 1) ^ s)] = l1;
        }
        if (bact) {
            unsigned h0, l0, h1, l1, h2, l2, h3, l3;
            split2(rb0.x, rb1.x, h0, l0);
            split2(rb0.y, rb1.y, h1, l1);
            split2(rb0.z, rb1.z, h2, l2);
            split2(rb0.w, rb1.w, h3, l3);
            *(uint4*)&Bh[kpw * B_STR + nq] = make_uint4(h0, h1, h2, h3);
            *(uint4*)&Bl[kpw * B_STR + nq] = make_uint4(l0, l1, l2, l3);
        }
        __syncthreads();
        if (kt + 16 < IDIM) {
            ra0 = *(const float4*)(aptr[0] + kt + 16);
            ra1 = *(const float4*)(aptr[1] + kt + 16);
            if (bact) {
                rb0 = *(const float4*)(bp + (size_t)(kt + 16) * ND);
                rb1 = *(const float4*)(bp + (size_t)(kt + 17) * ND);
            }
        }
        {
            unsigned ah[2][4], al[2][4];
            #pragma unroll
            for (int mt = 0; mt < 2; mt++) {
                int R = warpM * 32 + mt * 16 + gq;
                int base = R * 8;
                int c0 = tq ^ gq, c1 = (tq + 4) ^ gq;
                ah[mt][0] = Ah[base + c0];
                ah[mt][1] = Ah[base + 64 + c0];
                ah[mt][2] = Ah[base + c1];
                ah[mt][3] = Ah[base + 64 + c1];
                al[mt][0] = Al[base + c0];
                al[mt][1] = Al[base + 64 + c0];
                al[mt][2] = Al[base + c1];
                al[mt][3] = Al[base + 64 + c1];
            }
            #pragma unroll
            for (int nt = 0; nt < 4; nt++) {
                int c = warpN * 32 + nt * 8 + gq;
                unsigned bh[2], bl[2];
                bh[0] = Bh[tq * B_STR + c]; bh[1] = Bh[(tq + 4) * B_STR + c];
                bl[0] = Bl[tq * B_STR + c]; bl[1] = Bl[(tq + 4) * B_STR + c];
                #pragma unroll
                for (int mt = 0; mt < 2; mt++) {
                    mma_bf16(acc[mt][nt], ah[mt], bh);
                    mma_bf16(acc[mt][nt], al[mt], bh);
                    mma_bf16(acc[mt][nt], ah[mt], bl);
                }
            }
        }
        __syncthreads();
    }
    // epilogue
    #pragma unroll
    for (int mt = 0; mt < 2; mt++) {
        #pragma unroll
        for (int half = 0; half < 2; half++) {
            int r = m0 + warpM * 32 + mt * 16 + half * 8 + gq;
            if (r >= cnt) continue;
            if (ROUTED) {
                int grow = off + r;
                int tok  = g_rowlist[grow];
                float w  = g_roww[grow] * 2.5f;   // routed scaling
                float* op = out + (size_t)tok * ND + n0 + warpN * 32;
                #pragma unroll
                for (int nt = 0; nt < 4; nt++) {
                    atomicAdd(&op[nt * 8 + 2 * tq],     w * acc[mt][nt][half * 2 + 0]);
                    atomicAdd(&op[nt * 8 + 2 * tq + 1], w * acc[mt][nt][half * 2 + 1]);
                }
            } else {
                float* op = out + (size_t)r * ND + n0 + warpN * 32;
                #pragma unroll
                for (int nt = 0; nt < 4; nt++) {
                    float2 v;
                    v.x = acc[mt][nt][half * 2 + 0];
                    v.y = acc[mt][nt][half * 2 + 1];
                    *(float2*)&op[nt * 8 + 2 * tq] = v;
                }
            }
        }
    }
}

// ---------------- launch ----------------
extern "C" void kernel_launch(void* const* d_in, const int* in_sizes, int n_in,
                              void* d_out, int out_size) {
    const float* x       = (const float*)d_in[0];
    const float* gate_w  = (const float*)d_in[1];
    const float* gate_b  = (const float*)d_in[2];
    const float* w_gate  = (const float*)d_in[3];
    const float* w_up    = (const float*)d_in[4];
    const float* w_down  = (const float*)d_in[5];
    const float* sw_gate = (const float*)d_in[6];
    const float* sw_up   = (const float*)d_in[7];
    const float* sw_down = (const float*)d_in[8];
    float* out = (float*)d_out;

    zero_kernel   <<<1, 32>>>();
    gate_kernel   <<<NT, 256>>>(x, gate_w, gate_b);
    scan_kernel   <<<1, 32>>>();
    scatter_kernel<<<NA / 256, 256>>>();

    // shared expert: gate/up then down (down WRITES out -> must precede routed atomics)
    gemm_gated<NSI, false><<<dim3(NT / 128, NSI / 64, 1), 256>>>(x, sw_gate, sw_up);
    // routed experts: gate/up
    gemm_gated<NI,  true ><<<dim3(NT / 128, NI  / 64, NE), 256>>>(x, w_gate, w_up);
    // shared down-proj: plain stores initialize out
    gemm_down<NSI, false><<<dim3(NT / 128, ND / 64, 1), 256>>>(sw_down, out);
    // routed down-proj: weighted atomic accumulation into out
    gemm_down<NI,  true ><<<dim3(NT / 128, ND / 64, NE), 256>>>(w_down, out);
}